// round 12
// baseline (speedup 1.0000x reference)
#include <cuda_runtime.h>
#include <cuda_bf16.h>
#include <cstdint>

#define DEVINL __device__ __forceinline__

static constexpr int NN = 16384;   // nodes
static constexpr int DF = 256;     // feature dim == out dim
static constexpr int K2 = 1024;    // GEMM2 K: [f_hi | f_hi | f_lo | neigh]

// ---------------- scratch (device globals; no allocation allowed) -----------
__device__ __align__(128) __nv_bfloat16 g_fT[(size_t)DF * NN];   // 8 MB  features^T bf16
__device__ __align__(128) __nv_bfloat16 g_A2[(size_t)NN * K2];   // 32 MB GEMM2 A operand
__device__ __align__(128) __nv_bfloat16 g_B2[(size_t)DF * K2];   // 512 KB GEMM2 B operand

// ---------------- PTX helpers (all legal at compute_103 virtual arch) -------
DEVINL uint32_t smem_u32(const void* p) {
    uint32_t a;
    asm("{ .reg .u64 t; cvta.to.shared.u64 t, %1; cvt.u32.u64 %0, t; }"
        : "=r"(a) : "l"(p));
    return a;
}
DEVINL void cp16(uint32_t dst, const void* src) {
    asm volatile("cp.async.cg.shared.global [%0], [%1], 16;"
                 :: "r"(dst), "l"(src) : "memory");
}
DEVINL void cp_commit() { asm volatile("cp.async.commit_group;" ::: "memory"); }
template <int N> DEVINL void cp_wait() {
    asm volatile("cp.async.wait_group %0;" :: "n"(N) : "memory");
}
DEVINL void ldsm4(uint32_t* r, uint32_t a) {
    asm volatile("ldmatrix.sync.aligned.m8n8.x4.shared.b16 {%0,%1,%2,%3}, [%4];"
                 : "=r"(r[0]), "=r"(r[1]), "=r"(r[2]), "=r"(r[3]) : "r"(a));
}
DEVINL void sts128(uint32_t a, uint32_t x, uint32_t y, uint32_t z, uint32_t w) {
    asm volatile("st.shared.v4.b32 [%0], {%1,%2,%3,%4};"
                 :: "r"(a), "r"(x), "r"(y), "r"(z), "r"(w));
}
DEVINL void mma16816(float* d, const uint32_t* a, uint32_t b0, uint32_t b1) {
    asm volatile(
        "mma.sync.aligned.m16n8k16.row.col.f32.bf16.bf16.f32 "
        "{%0,%1,%2,%3}, {%4,%5,%6,%7}, {%8,%9}, {%0,%1,%2,%3};"
        : "+f"(d[0]), "+f"(d[1]), "+f"(d[2]), "+f"(d[3])
        : "r"(a[0]), "r"(a[1]), "r"(a[2]), "r"(a[3]), "r"(b0), "r"(b1));
}
DEVINL uint32_t packbf2(float x, float y) {
    __nv_bfloat162 h = __floats2bfloat162_rn(x, y);
    return *reinterpret_cast<uint32_t*>(&h);
}
DEVINL float4 ldcs4(const float* p) {
    float4 v;
    asm volatile("ld.global.cs.v4.f32 {%0,%1,%2,%3}, [%4];"
                 : "=f"(v.x), "=f"(v.y), "=f"(v.z), "=f"(v.w) : "l"(p));
    return v;
}

// ---------------- prep kernels ----------------------------------------------

// features^T (bf16) via tiled transpose. grid(512, 8), block(32, 8)
__global__ void prep_fT(const float* __restrict__ f) {
    __shared__ __nv_bfloat16 tile[32][33];
    const int i0 = blockIdx.x * 32, d0 = blockIdx.y * 32;
    const int tx = threadIdx.x, ty = threadIdx.y;
#pragma unroll
    for (int k = 0; k < 32; k += 8)
        tile[ty + k][tx] = __float2bfloat16(f[(size_t)(i0 + ty + k) * DF + d0 + tx]);
    __syncthreads();
#pragma unroll
    for (int k = 0; k < 32; k += 8)
        g_fT[(size_t)(d0 + ty + k) * NN + i0 + tx] = tile[tx][ty + k];
}

// A2 = [f_hi | f_hi | f_lo | (neigh filled by GEMM1 epilogue)]
__global__ void __launch_bounds__(256) prep_A2(const float* __restrict__ f) {
    const int i = blockIdx.x, d = threadIdx.x;
    const float v = f[(size_t)i * DF + d];
    const __nv_bfloat16 h = __float2bfloat16(v);
    const size_t b = (size_t)i * K2;
    g_A2[b + d]       = h;
    g_A2[b + 256 + d] = h;
    g_A2[b + 512 + d] = __float2bfloat16(v - __bfloat162float(h));
}

// B2 = [W1_hi | W1_lo | W1_hi | W2]
__global__ void __launch_bounds__(256) prep_W(const float* __restrict__ W) {
    const int o = blockIdx.x, c = threadIdx.x;
    const float w1 = W[(size_t)o * 512 + c];
    const __nv_bfloat16 h = __float2bfloat16(w1);
    const size_t b = (size_t)o * K2;
    g_B2[b + c]       = h;
    g_B2[b + 256 + c] = __float2bfloat16(w1 - __bfloat162float(h));
    g_B2[b + 512 + c] = h;
    g_B2[b + 768 + c] = __float2bfloat16(W[(size_t)o * 512 + 256 + c]);
}

// ---------------- mma.sync GEMM ----------------------------------------------
// MODE 1: BM=64, BN=256, 256 thr (8 warps, 2Mx4N, warp tile 32x64), 2 CTAs/SM.
//         C = bf16(adj_f32) @ fT^T; fused row-sum -> inv_deg; epilogue scales,
//         writes bf16 neigh into g_A2[:, 768:1024].  A: 2-stage LDG->cvt->STS,
//         B: 3-stage cp.async, wait_group<1>.  Warps process the 4 k-steps in
//         rotated order (start = warp&3) to desynchronize LDSM bursts.
// MODE 2: BM=64, BN=256, 256 thr, 2 CTAs/SM, 2-stage double buffer on both
//         operands.  C = A2 @ B2^T (K=1024 hi/lo split); epilogue fp32 out.
static constexpr int BN = 256, BK = 64;
static constexpr int BBYTES = BN * BK * 2;                   // 32 KB / stage
static constexpr int BMm = 64;
static constexpr int ABYTES = BMm * BK * 2;                  // 8 KB / stage

template <int MODE>
__global__ void __launch_bounds__(256, 2)
gemm_mma(float* __restrict__ outF, const float* __restrict__ adjF) {
    constexpr int  THREADS = 256;
    constexpr int  KT      = (MODE == 1) ? (NN / BK) : (K2 / BK);
    constexpr long ldb     = (MODE == 1) ? NN : K2;
    constexpr int  ASTG    = 2;
    constexpr int  BSTG    = (MODE == 1) ? 3 : 2;
    constexpr int  PREF    = (MODE == 1) ? 2 : 1;   // groups committed ahead
    constexpr int  NB_T    = BBYTES / 16 / THREADS; // 8
    constexpr int  NA_T    = ABYTES / 16 / THREADS; // 2 (mode2)
    constexpr int  RSTRIDE = THREADS / 8;           // 32 rows per t-step
    constexpr uint32_t A_OFF = 0;
    constexpr uint32_t B_OFF = ASTG * ABYTES;
    const __nv_bfloat16* __restrict__ Bg = (MODE == 1) ? g_fT : g_B2;

    extern __shared__ char smraw[];
    __shared__ float sdeg[BMm];
    const uint32_t sb = (smem_u32(smraw) + 127u) & ~127u;

    const int tid  = threadIdx.x;
    const int lane = tid & 31;
    const int w    = tid >> 5;
    const int wm   = w >> 2;            // 0..1  (M dir)
    const int wn   = w & 3;             // 0..3  (N dir)
    const long m0  = (long)blockIdx.x * BMm;

    float acc[2][8][4];
#pragma unroll
    for (int i = 0; i < 2; i++)
#pragma unroll
        for (int j = 0; j < 8; j++)
#pragma unroll
            for (int k = 0; k < 4; k++) acc[i][j][k] = 0.f;

    // ---- B loader state (induction) ----
    const int rowB = tid >> 3, cB = tid & 7;
    const __nv_bfloat16* pBg = Bg + (size_t)rowB * ldb + cB * 8;   // next tile
    const uint32_t offB = (uint32_t)rowB * 128u +
                          ((uint32_t)(cB ^ (rowB & 7)) << 4);
    uint32_t dstB = sb + B_OFF;                                    // stage cursor
    auto cpB = [&]() {                                             // loads next tile
#pragma unroll
        for (int t = 0; t < NB_T; t++)
            cp16(dstB + offB + (uint32_t)t * (RSTRIDE * 128u),
                 pBg + (size_t)t * RSTRIDE * ldb);
        pBg  += BK;
        dstB += BBYTES;
        if (dstB == sb + B_OFF + BSTG * BBYTES) dstB = sb + B_OFF;
    };

    // ---- A loader state, MODE2 (induction) ----
    const __nv_bfloat16* pA2g = g_A2 + (m0 + rowB) * (size_t)K2 + cB * 8;
    uint32_t dstA = sb + A_OFF;
    auto cpA2 = [&]() {
#pragma unroll
        for (int t = 0; t < NA_T; t++)
            cp16(dstA + offB + (uint32_t)t * (RSTRIDE * 128u),
                 pA2g + (size_t)t * RSTRIDE * K2);
        pA2g += BK;
        dstA += ABYTES;
        if (dstA == sb + A_OFF + ASTG * ABYTES) dstA = sb + A_OFF;
    };

    // ---- A staging, MODE1: LDG f32 -> rowsum + packed bf16 regs -> STS -----
    uint32_t rP[8];                     // 16 bf16 (packed) = this thread's slice
    float    rowsum = 0.f;
    const int arow = tid >> 2;          // 0..63 (4 threads per row)
    const int aq   = tid & 3;           // cols aq*16 .. aq*16+15
    const float* pA = adjF + (m0 + arow) * (long)NN + aq * 16;     // next tile
    auto ldgA = [&]() {
#pragma unroll
        for (int j = 0; j < 4; j++) {
            float4 v = ldcs4(pA + j * 4);
            rowsum += (v.x + v.y) + (v.z + v.w);     // exact f32 degree
            rP[2 * j]     = packbf2(v.x, v.y);
            rP[2 * j + 1] = packbf2(v.z, v.w);
        }
        pA += BK;
    };
    // stsA: second chunk offset = first ^ 16 (c even -> (c+1)^rs == (c^rs)^1)
    const uint32_t sA0 = sb + A_OFF + (uint32_t)arow * 128u +
                         ((uint32_t)((aq * 2) ^ (arow & 7)) << 4);
    auto stsA = [&](int s) {
        const uint32_t a0 = sA0 + (uint32_t)s * ABYTES;
        sts128(a0,      rP[0], rP[1], rP[2], rP[3]);
        sts128(a0 ^ 16, rP[4], rP[5], rP[6], rP[7]);
    };

    // ---- ldmatrix fragment row terms (computed once) ----
    const int lhi  = lane >> 4;                       // chunk parity
    uint32_t rtA[2], rtB[4];
#pragma unroll
    for (int mi = 0; mi < 2; mi++) {
        const int row = wm * 32 + (lane & 15) + mi * 16;
        rtA[mi] = (uint32_t)row * 128u | ((uint32_t)(row & 7) << 4);
    }
#pragma unroll
    for (int nb = 0; nb < 4; nb++) {
        const int row = wn * 64 + (lane & 15) + nb * 16;
        rtB[nb] = (uint32_t)row * 128u | ((uint32_t)(row & 7) << 4);
    }

    // one k-step of the warp tile (any order across ks is valid; f32 acc)
    auto computeKs = [&](uint32_t aBase, uint32_t bBase, int ks) {
        const uint32_t cx = (uint32_t)(ks * 2 + lhi) << 4;
        uint32_t af[2][4], bf[4][4];
#pragma unroll
        for (int mi = 0; mi < 2; mi++) ldsm4(af[mi], (aBase + rtA[mi]) ^ cx);
#pragma unroll
        for (int nb = 0; nb < 4; nb++) ldsm4(bf[nb], (bBase + rtB[nb]) ^ cx);
#pragma unroll
        for (int mi = 0; mi < 2; mi++)
#pragma unroll
            for (int nb = 0; nb < 4; nb++) {
                mma16816(acc[mi][nb * 2],     af[mi], bf[nb][0], bf[nb][2]);
                mma16816(acc[mi][nb * 2 + 1], af[mi], bf[nb][1], bf[nb][3]);
            }
    };
    const int ksrot = w & 3;            // per-warp k-step phase rotation

    // ---------------- prologue: commit PREF groups --------------------------
    if constexpr (MODE == 1) {
        ldgA(); stsA(0);                // tile 0 A into stage 0
        ldgA();                         // tile 1 A staged in regs (packed)
        cpB(); cp_commit();             // tile 0 B -> stage 0
        cpB(); cp_commit();             // tile 1 B -> stage 1
    } else {
        cpA2(); cpB(); cp_commit();     // tile 0 -> stage 0
    }

    // ---------------- main loop ----------------
    // MODE1 invariant at top of iter kt: committed groups = {kt, kt+1}.
    // wait<1> -> tile kt complete. Refill stage (kt+2)%3 == (kt-1)%3 was last
    // read at iter kt-1; the barrier proves all warps finished it. stsA target
    // stage (kt+1)%2 likewise. Loads issue after ONE k-step (1+3 split) so the
    // async work overlaps maximally with the remaining compute.
    // MODE2 (double buffer): wait<0> -> tile kt resident; immediately issue
    // tile kt+1 into the other stage (read at kt-1, barrier-covered), then
    // compute tile kt while it flies.
    uint32_t cAs = sb + A_OFF;          // compute stage cursors (tile kt)
    uint32_t cBs = sb + B_OFF;
    for (int kt = 0; kt < KT; kt++) {
        cp_wait<PREF - 1>();
        __syncthreads();
        if constexpr (MODE == 1) {
            computeKs(cAs, cBs, ksrot);                 // 1st (rotated) k-step
            if (kt + 2 < KT) cpB();
            cp_commit();                                // one group per iter
            if (kt + 1 < KT) stsA((kt + 1) & 1);        // rP holds tile kt+1
            if (kt + 2 < KT) ldgA();
            computeKs(cAs, cBs, (ksrot + 1) & 3);
            computeKs(cAs, cBs, (ksrot + 2) & 3);
            computeKs(cAs, cBs, (ksrot + 3) & 3);
        } else {
            if (kt + 1 < KT) { cpA2(); cpB(); }
            cp_commit();
            computeKs(cAs, cBs, ksrot);
            computeKs(cAs, cBs, (ksrot + 1) & 3);
            computeKs(cAs, cBs, (ksrot + 2) & 3);
            computeKs(cAs, cBs, (ksrot + 3) & 3);
        }
        cAs += ABYTES;
        if (cAs == sb + A_OFF + ASTG * ABYTES) cAs = sb + A_OFF;
        cBs += BBYTES;
        if (cBs == sb + B_OFF + BSTG * BBYTES) cBs = sb + B_OFF;
    }

    // ---------------- epilogue ----------------
    if constexpr (MODE == 1) {
        rowsum += __shfl_xor_sync(0xFFFFFFFFu, rowsum, 1);
        rowsum += __shfl_xor_sync(0xFFFFFFFFu, rowsum, 2);
        if ((tid & 3) == 0) sdeg[tid >> 2] = 1.0f / (rowsum + 1.0f);
        __syncthreads();
    }

#pragma unroll
    for (int mi = 0; mi < 2; mi++) {
        const int rl = wm * 32 + mi * 16 + (lane >> 2);
        const float slo = (MODE == 1) ? sdeg[rl]     : 1.f;
        const float shi = (MODE == 1) ? sdeg[rl + 8] : 1.f;
        const long glo = m0 + rl, ghi = glo + 8;
#pragma unroll
        for (int ni = 0; ni < 8; ni++) {
            const int col = wn * 64 + ni * 8 + (lane & 3) * 2;
            const float* a = acc[mi][ni];
            if constexpr (MODE == 1) {
                *reinterpret_cast<uint32_t*>(g_A2 + glo * K2 + 768 + col) =
                    packbf2(a[0] * slo, a[1] * slo);
                *reinterpret_cast<uint32_t*>(g_A2 + ghi * K2 + 768 + col) =
                    packbf2(a[2] * shi, a[3] * shi);
            } else {
                *reinterpret_cast<float2*>(outF + glo * DF + col) =
                    make_float2(a[0], a[1]);
                *reinterpret_cast<float2*>(outF + ghi * DF + col) =
                    make_float2(a[2], a[3]);
            }
        }
    }
}

static constexpr uint32_t SMEM1 = 2 * ABYTES + 3 * BBYTES + 128; // ~112.1 KB
static constexpr uint32_t SMEM2 = 2 * ABYTES + 2 * BBYTES + 128; // ~80.1 KB

// ---------------- launch -----------------------------------------------------
extern "C" void kernel_launch(void* const* d_in, const int* in_sizes, int n_in,
                              void* d_out, int out_size) {
    const float* features = nullptr;
    const float* adj      = nullptr;
    const float* W        = nullptr;
    for (int i = 0; i < n_in; i++) {
        if (in_sizes[i] == NN * DF)          features = (const float*)d_in[i];
        else if (in_sizes[i] == DF * 2 * DF) W        = (const float*)d_in[i];
        else                                  adj      = (const float*)d_in[i];
    }

    cudaFuncSetAttribute(gemm_mma<1>, cudaFuncAttributeMaxDynamicSharedMemorySize, SMEM1);
    cudaFuncSetAttribute(gemm_mma<2>, cudaFuncAttributeMaxDynamicSharedMemorySize, SMEM2);

    prep_fT<<<dim3(NN / 32, DF / 32), dim3(32, 8)>>>(features);
    prep_A2<<<NN, 256>>>(features);
    prep_W<<<DF, 256>>>(W);
    gemm_mma<1><<<NN / BMm, 256, SMEM1>>>(nullptr, adj);
    gemm_mma<2><<<NN / BMm, 256, SMEM2>>>((float*)d_out, nullptr);
}

// round 13
// speedup vs baseline: 1.0409x; 1.0409x over previous
#include <cuda_runtime.h>
#include <cuda_bf16.h>
#include <cstdint>

#define DEVINL __device__ __forceinline__

static constexpr int NN = 16384;   // nodes
static constexpr int DF = 256;     // feature dim == out dim
static constexpr int K2 = 1024;    // GEMM2 K: [f_hi | f_hi | f_lo | neigh]

// ---------------- scratch (device globals; no allocation allowed) -----------
__device__ __align__(128) __nv_bfloat16 g_fT[(size_t)DF * NN];   // 8 MB  features^T bf16
__device__ __align__(128) __nv_bfloat16 g_A2[(size_t)NN * K2];   // 32 MB GEMM2 A operand
__device__ __align__(128) __nv_bfloat16 g_B2[(size_t)DF * K2];   // 512 KB GEMM2 B operand

// ---------------- PTX helpers (all legal at compute_103 virtual arch) -------
DEVINL uint32_t smem_u32(const void* p) {
    uint32_t a;
    asm("{ .reg .u64 t; cvta.to.shared.u64 t, %1; cvt.u32.u64 %0, t; }"
        : "=r"(a) : "l"(p));
    return a;
}
DEVINL void cp16(uint32_t dst, const void* src) {
    asm volatile("cp.async.cg.shared.global [%0], [%1], 16;"
                 :: "r"(dst), "l"(src) : "memory");
}
DEVINL void cp_commit() { asm volatile("cp.async.commit_group;" ::: "memory"); }
template <int N> DEVINL void cp_wait() {
    asm volatile("cp.async.wait_group %0;" :: "n"(N) : "memory");
}
DEVINL void ldsm4(uint32_t* r, uint32_t a) {
    asm volatile("ldmatrix.sync.aligned.m8n8.x4.shared.b16 {%0,%1,%2,%3}, [%4];"
                 : "=r"(r[0]), "=r"(r[1]), "=r"(r[2]), "=r"(r[3]) : "r"(a));
}
DEVINL void sts128(uint32_t a, uint32_t x, uint32_t y, uint32_t z, uint32_t w) {
    asm volatile("st.shared.v4.b32 [%0], {%1,%2,%3,%4};"
                 :: "r"(a), "r"(x), "r"(y), "r"(z), "r"(w));
}
DEVINL void mma16816(float* d, const uint32_t* a, uint32_t b0, uint32_t b1) {
    asm volatile(
        "mma.sync.aligned.m16n8k16.row.col.f32.bf16.bf16.f32 "
        "{%0,%1,%2,%3}, {%4,%5,%6,%7}, {%8,%9}, {%0,%1,%2,%3};"
        : "+f"(d[0]), "+f"(d[1]), "+f"(d[2]), "+f"(d[3])
        : "r"(a[0]), "r"(a[1]), "r"(a[2]), "r"(a[3]), "r"(b0), "r"(b1));
}
DEVINL uint32_t packbf2(float x, float y) {
    __nv_bfloat162 h = __floats2bfloat162_rn(x, y);
    return *reinterpret_cast<uint32_t*>(&h);
}
DEVINL float4 ldcs4(const float* p) {
    float4 v;
    asm volatile("ld.global.cs.v4.f32 {%0,%1,%2,%3}, [%4];"
                 : "=f"(v.x), "=f"(v.y), "=f"(v.z), "=f"(v.w) : "l"(p));
    return v;
}
DEVINL void ldcs4u(uint32_t* r, const void* p) {
    asm volatile("ld.global.cs.v4.b32 {%0,%1,%2,%3}, [%4];"
                 : "=r"(r[0]), "=r"(r[1]), "=r"(r[2]), "=r"(r[3]) : "l"(p));
}

// ---------------- prep kernels ----------------------------------------------

// features^T (bf16) via tiled transpose. grid(512, 8), block(32, 8)
__global__ void prep_fT(const float* __restrict__ f) {
    __shared__ __nv_bfloat16 tile[32][33];
    const int i0 = blockIdx.x * 32, d0 = blockIdx.y * 32;
    const int tx = threadIdx.x, ty = threadIdx.y;
#pragma unroll
    for (int k = 0; k < 32; k += 8)
        tile[ty + k][tx] = __float2bfloat16(f[(size_t)(i0 + ty + k) * DF + d0 + tx]);
    __syncthreads();
#pragma unroll
    for (int k = 0; k < 32; k += 8)
        g_fT[(size_t)(d0 + ty + k) * NN + i0 + tx] = tile[tx][ty + k];
}

// A2 = [f_hi | f_hi | f_lo | (neigh filled by GEMM1 epilogue)]
__global__ void __launch_bounds__(256) prep_A2(const float* __restrict__ f) {
    const int i = blockIdx.x, d = threadIdx.x;
    const float v = f[(size_t)i * DF + d];
    const __nv_bfloat16 h = __float2bfloat16(v);
    const size_t b = (size_t)i * K2;
    g_A2[b + d]       = h;
    g_A2[b + 256 + d] = h;
    g_A2[b + 512 + d] = __float2bfloat16(v - __bfloat162float(h));
}

// B2 = [W1_hi | W1_lo | W1_hi | W2]
__global__ void __launch_bounds__(256) prep_W(const float* __restrict__ W) {
    const int o = blockIdx.x, c = threadIdx.x;
    const float w1 = W[(size_t)o * 512 + c];
    const __nv_bfloat16 h = __float2bfloat16(w1);
    const size_t b = (size_t)o * K2;
    g_B2[b + c]       = h;
    g_B2[b + 256 + c] = __float2bfloat16(w1 - __bfloat162float(h));
    g_B2[b + 512 + c] = h;
    g_B2[b + 768 + c] = __float2bfloat16(W[(size_t)o * 512 + 256 + c]);
}

// ---------------- mma.sync GEMM ----------------------------------------------
// Shared skeleton, both modes: BM=64, BN=256, BK=64, 256 thr (8 warps, 2Mx4N,
// warp tile 32x64), 2 CTAs/SM.  A: 2-stage LDG->STS register staging,
// B: 3-stage cp.async, per-tile commit groups, wait_group<1> (PREF=2).
// MODE 1: C = bf16(adj_f32) @ fT^T; fused f32 row-sum -> inv_deg; epilogue
//         scales and writes bf16 neigh into g_A2[:, 768:1024].  KT=256.
// MODE 2: C = A2 @ B2^T (K=1024 hi/lo split); A loaded as raw bf16 (no
//         convert); epilogue writes fp32 out.  KT=16, grid=256.
static constexpr int BN = 256, BK = 64;
static constexpr int BBYTES = BN * BK * 2;                   // 32 KB / stage
static constexpr int BMm = 64;
static constexpr int ABYTES = BMm * BK * 2;                  // 8 KB / stage
static constexpr int ASTG = 2, BSTG = 3, PREF = 2;

template <int MODE>
__global__ void __launch_bounds__(256, 2)
gemm_mma(float* __restrict__ outF, const float* __restrict__ adjF) {
    constexpr int  THREADS = 256;
    constexpr int  KT      = (MODE == 1) ? (NN / BK) : (K2 / BK);
    constexpr long ldb     = (MODE == 1) ? NN : K2;
    constexpr int  NB_T    = BBYTES / 16 / THREADS; // 8
    constexpr int  RSTRIDE = THREADS / 8;           // 32 rows per t-step
    constexpr uint32_t A_OFF = 0;
    constexpr uint32_t B_OFF = ASTG * ABYTES;
    const __nv_bfloat16* __restrict__ Bg = (MODE == 1) ? g_fT : g_B2;

    extern __shared__ char smraw[];
    __shared__ float sdeg[BMm];
    const uint32_t sb = (smem_u32(smraw) + 127u) & ~127u;

    const int tid  = threadIdx.x;
    const int lane = tid & 31;
    const int w    = tid >> 5;
    const int wm   = w >> 2;            // 0..1  (M dir)
    const int wn   = w & 3;             // 0..3  (N dir)
    const long m0  = (long)blockIdx.x * BMm;

    float acc[2][8][4];
#pragma unroll
    for (int i = 0; i < 2; i++)
#pragma unroll
        for (int j = 0; j < 8; j++)
#pragma unroll
            for (int k = 0; k < 4; k++) acc[i][j][k] = 0.f;

    // ---- B loader state (induction) ----
    const int rowB = tid >> 3, cB = tid & 7;
    const __nv_bfloat16* pBg = Bg + (size_t)rowB * ldb + cB * 8;   // next tile
    const uint32_t offB = (uint32_t)rowB * 128u +
                          ((uint32_t)(cB ^ (rowB & 7)) << 4);
    uint32_t dstB = sb + B_OFF;                                    // stage cursor
    auto cpB = [&]() {                                             // loads next tile
#pragma unroll
        for (int t = 0; t < NB_T; t++)
            cp16(dstB + offB + (uint32_t)t * (RSTRIDE * 128u),
                 pBg + (size_t)t * RSTRIDE * ldb);
        pBg  += BK;
        dstB += BBYTES;
        if (dstB == sb + B_OFF + BSTG * BBYTES) dstB = sb + B_OFF;
    };

    // ---- A staging: LDG -> regs (rP, packed bf16) -> STS --------------------
    // MODE1: 4x float4 LDG of adj f32 + exact f32 rowsum + convert.
    // MODE2: 2x 16B LDG of bf16 A2 rows (passthrough).
    uint32_t rP[8];                     // 16 bf16 (packed) = this thread's slice
    float    rowsum = 0.f;
    const int arow = tid >> 2;          // 0..63 (4 threads per row)
    const int aq   = tid & 3;           // cols aq*16 .. aq*16+15
    const float*         pA1 = adjF ? adjF + (m0 + arow) * (long)NN + aq * 16 : nullptr;
    const __nv_bfloat16* pA2 = g_A2 + (m0 + arow) * (size_t)K2 + aq * 16;
    auto ldgA = [&]() {
        if constexpr (MODE == 1) {
#pragma unroll
            for (int j = 0; j < 4; j++) {
                float4 v = ldcs4(pA1 + j * 4);
                rowsum += (v.x + v.y) + (v.z + v.w);   // exact f32 degree
                rP[2 * j]     = packbf2(v.x, v.y);
                rP[2 * j + 1] = packbf2(v.z, v.w);
            }
            pA1 += BK;
        } else {
            ldcs4u(rP,     pA2);
            ldcs4u(rP + 4, pA2 + 8);
            pA2 += BK;
        }
    };
    // stsA: second chunk offset = first ^ 16 (c even -> (c+1)^rs == (c^rs)^1)
    const uint32_t sA0 = sb + A_OFF + (uint32_t)arow * 128u +
                         ((uint32_t)((aq * 2) ^ (arow & 7)) << 4);
    auto stsA = [&](int s) {
        const uint32_t a0 = sA0 + (uint32_t)s * ABYTES;
        sts128(a0,      rP[0], rP[1], rP[2], rP[3]);
        sts128(a0 ^ 16, rP[4], rP[5], rP[6], rP[7]);
    };

    // ---- ldmatrix fragment row terms (computed once) ----
    const int lhi  = lane >> 4;                       // chunk parity
    uint32_t rtA[2], rtB[4];
#pragma unroll
    for (int mi = 0; mi < 2; mi++) {
        const int row = wm * 32 + (lane & 15) + mi * 16;
        rtA[mi] = (uint32_t)row * 128u | ((uint32_t)(row & 7) << 4);
    }
#pragma unroll
    for (int nb = 0; nb < 4; nb++) {
        const int row = wn * 64 + (lane & 15) + nb * 16;
        rtB[nb] = (uint32_t)row * 128u | ((uint32_t)(row & 7) << 4);
    }

    auto compute = [&](uint32_t aBase, uint32_t bBase, int ks0, int ks1) {
#pragma unroll
        for (int ks = ks0; ks < ks1; ks++) {
            const uint32_t cx = (uint32_t)(ks * 2 + lhi) << 4;
            uint32_t af[2][4], bf[4][4];
#pragma unroll
            for (int mi = 0; mi < 2; mi++) ldsm4(af[mi], (aBase + rtA[mi]) ^ cx);
#pragma unroll
            for (int nb = 0; nb < 4; nb++) ldsm4(bf[nb], (bBase + rtB[nb]) ^ cx);
#pragma unroll
            for (int mi = 0; mi < 2; mi++)
#pragma unroll
                for (int nb = 0; nb < 4; nb++) {
                    mma16816(acc[mi][nb * 2],     af[mi], bf[nb][0], bf[nb][2]);
                    mma16816(acc[mi][nb * 2 + 1], af[mi], bf[nb][1], bf[nb][3]);
                }
        }
    };

    // ---------------- prologue: commit PREF groups --------------------------
    ldgA(); stsA(0);                // tile 0 A into stage 0
    ldgA();                         // tile 1 A staged in regs (packed)
    cpB(); cp_commit();             // tile 0 B -> stage 0
    cpB(); cp_commit();             // tile 1 B -> stage 1

    // ---------------- main loop ----------------
    // Invariant at top of iter kt: committed groups = {kt, kt+1}.
    // wait<1> -> tile kt complete. Refill stage (kt+2)%3 == (kt-1)%3 was last
    // read at iter kt-1; the barrier proves all warps finished it. stsA target
    // stage (kt+1)%2 likewise. Loads issue mid-tile (between ks 0-1 and 2-3).
    uint32_t cAs = sb + A_OFF;          // compute stage cursors (tile kt)
    uint32_t cBs = sb + B_OFF;
    for (int kt = 0; kt < KT; kt++) {
        cp_wait<PREF - 1>();
        __syncthreads();
        compute(cAs, cBs, 0, 2);                    // ks 0,1 (data resident)
        if (kt + 2 < KT) cpB();
        cp_commit();                    // exactly one group per iteration
        if (kt + 1 < KT) stsA((kt + 1) & 1);        // rP holds tile kt+1
        if (kt + 2 < KT) ldgA();
        compute(cAs, cBs, 2, 4);                    // ks 2,3
        cAs += ABYTES;
        if (cAs == sb + A_OFF + ASTG * ABYTES) cAs = sb + A_OFF;
        cBs += BBYTES;
        if (cBs == sb + B_OFF + BSTG * BBYTES) cBs = sb + B_OFF;
    }

    // ---------------- epilogue ----------------
    if constexpr (MODE == 1) {
        rowsum += __shfl_xor_sync(0xFFFFFFFFu, rowsum, 1);
        rowsum += __shfl_xor_sync(0xFFFFFFFFu, rowsum, 2);
        if ((tid & 3) == 0) sdeg[tid >> 2] = 1.0f / (rowsum + 1.0f);
        __syncthreads();
    }

#pragma unroll
    for (int mi = 0; mi < 2; mi++) {
        const int rl = wm * 32 + mi * 16 + (lane >> 2);
        const float slo = (MODE == 1) ? sdeg[rl]     : 1.f;
        const float shi = (MODE == 1) ? sdeg[rl + 8] : 1.f;
        const long glo = m0 + rl, ghi = glo + 8;
#pragma unroll
        for (int ni = 0; ni < 8; ni++) {
            const int col = wn * 64 + ni * 8 + (lane & 3) * 2;
            const float* a = acc[mi][ni];
            if constexpr (MODE == 1) {
                *reinterpret_cast<uint32_t*>(g_A2 + glo * K2 + 768 + col) =
                    packbf2(a[0] * slo, a[1] * slo);
                *reinterpret_cast<uint32_t*>(g_A2 + ghi * K2 + 768 + col) =
                    packbf2(a[2] * shi, a[3] * shi);
            } else {
                *reinterpret_cast<float2*>(outF + glo * DF + col) =
                    make_float2(a[0], a[1]);
                *reinterpret_cast<float2*>(outF + ghi * DF + col) =
                    make_float2(a[2], a[3]);
            }
        }
    }
}

static constexpr uint32_t SMEM1 = ASTG * ABYTES + BSTG * BBYTES + 128; // ~112.1 KB

// ---------------- launch -----------------------------------------------------
extern "C" void kernel_launch(void* const* d_in, const int* in_sizes, int n_in,
                              void* d_out, int out_size) {
    const float* features = nullptr;
    const float* adj      = nullptr;
    const float* W        = nullptr;
    for (int i = 0; i < n_in; i++) {
        if (in_sizes[i] == NN * DF)          features = (const float*)d_in[i];
        else if (in_sizes[i] == DF * 2 * DF) W        = (const float*)d_in[i];
        else                                  adj      = (const float*)d_in[i];
    }

    cudaFuncSetAttribute(gemm_mma<1>, cudaFuncAttributeMaxDynamicSharedMemorySize, SMEM1);
    cudaFuncSetAttribute(gemm_mma<2>, cudaFuncAttributeMaxDynamicSharedMemorySize, SMEM1);

    prep_fT<<<dim3(NN / 32, DF / 32), dim3(32, 8)>>>(features);
    prep_A2<<<NN, 256>>>(features);
    prep_W<<<DF, 256>>>(W);
    gemm_mma<1><<<NN / BMm, 256, SMEM1>>>(nullptr, adj);
    gemm_mma<2><<<NN / BMm, 256, SMEM1>>>((float*)d_out, nullptr);
}

// round 14
// speedup vs baseline: 1.0449x; 1.0038x over previous
#include <cuda_runtime.h>
#include <cuda_bf16.h>
#include <cstdint>

#define DEVINL __device__ __forceinline__

static constexpr int NN = 16384;   // nodes
static constexpr int DF = 256;     // feature dim == out dim
static constexpr int K2 = 1024;    // GEMM2 K: [f_hi | f_hi | f_lo | neigh]

// ---------------- scratch (device globals; no allocation allowed) -----------
__device__ __align__(128) __nv_bfloat16 g_fT[(size_t)DF * NN];   // 8 MB  features^T bf16
__device__ __align__(128) __nv_bfloat16 g_A2[(size_t)NN * K2];   // 32 MB GEMM2 A operand
__device__ __align__(128) __nv_bfloat16 g_B2[(size_t)DF * K2];   // 512 KB GEMM2 B operand

// ---------------- PTX helpers (all legal at compute_103 virtual arch) -------
DEVINL uint32_t smem_u32(const void* p) {
    uint32_t a;
    asm("{ .reg .u64 t; cvta.to.shared.u64 t, %1; cvt.u32.u64 %0, t; }"
        : "=r"(a) : "l"(p));
    return a;
}
DEVINL void cp16(uint32_t dst, const void* src) {
    asm volatile("cp.async.cg.shared.global [%0], [%1], 16;"
                 :: "r"(dst), "l"(src) : "memory");
}
DEVINL void cp_commit() { asm volatile("cp.async.commit_group;" ::: "memory"); }
template <int N> DEVINL void cp_wait() {
    asm volatile("cp.async.wait_group %0;" :: "n"(N) : "memory");
}
DEVINL void ldsm4(uint32_t* r, uint32_t a) {
    asm volatile("ldmatrix.sync.aligned.m8n8.x4.shared.b16 {%0,%1,%2,%3}, [%4];"
                 : "=r"(r[0]), "=r"(r[1]), "=r"(r[2]), "=r"(r[3]) : "r"(a));
}
DEVINL void sts128(uint32_t a, uint32_t x, uint32_t y, uint32_t z, uint32_t w) {
    asm volatile("st.shared.v4.b32 [%0], {%1,%2,%3,%4};"
                 :: "r"(a), "r"(x), "r"(y), "r"(z), "r"(w));
}
DEVINL void mma16816(float* d, const uint32_t* a, uint32_t b0, uint32_t b1) {
    asm volatile(
        "mma.sync.aligned.m16n8k16.row.col.f32.bf16.bf16.f32 "
        "{%0,%1,%2,%3}, {%4,%5,%6,%7}, {%8,%9}, {%0,%1,%2,%3};"
        : "+f"(d[0]), "+f"(d[1]), "+f"(d[2]), "+f"(d[3])
        : "r"(a[0]), "r"(a[1]), "r"(a[2]), "r"(a[3]), "r"(b0), "r"(b1));
}
DEVINL uint32_t packbf2(float x, float y) {
    __nv_bfloat162 h = __floats2bfloat162_rn(x, y);
    return *reinterpret_cast<uint32_t*>(&h);
}
DEVINL float4 ldcs4(const float* p) {
    float4 v;
    asm volatile("ld.global.cs.v4.f32 {%0,%1,%2,%3}, [%4];"
                 : "=f"(v.x), "=f"(v.y), "=f"(v.z), "=f"(v.w) : "l"(p));
    return v;
}

// ---------------- prep kernels ----------------------------------------------

// features^T (bf16) via tiled transpose. grid(512, 8), block(32, 8)
__global__ void prep_fT(const float* __restrict__ f) {
    __shared__ __nv_bfloat16 tile[32][33];
    const int i0 = blockIdx.x * 32, d0 = blockIdx.y * 32;
    const int tx = threadIdx.x, ty = threadIdx.y;
#pragma unroll
    for (int k = 0; k < 32; k += 8)
        tile[ty + k][tx] = __float2bfloat16(f[(size_t)(i0 + ty + k) * DF + d0 + tx]);
    __syncthreads();
#pragma unroll
    for (int k = 0; k < 32; k += 8)
        g_fT[(size_t)(d0 + ty + k) * NN + i0 + tx] = tile[tx][ty + k];
}

// A2 = [f_hi | f_hi | f_lo | (neigh filled by GEMM1 epilogue)]
__global__ void __launch_bounds__(256) prep_A2(const float* __restrict__ f) {
    const int i = blockIdx.x, d = threadIdx.x;
    const float v = f[(size_t)i * DF + d];
    const __nv_bfloat16 h = __float2bfloat16(v);
    const size_t b = (size_t)i * K2;
    g_A2[b + d]       = h;
    g_A2[b + 256 + d] = h;
    g_A2[b + 512 + d] = __float2bfloat16(v - __bfloat162float(h));
}

// B2 = [W1_hi | W1_lo | W1_hi | W2]
__global__ void __launch_bounds__(256) prep_W(const float* __restrict__ W) {
    const int o = blockIdx.x, c = threadIdx.x;
    const float w1 = W[(size_t)o * 512 + c];
    const __nv_bfloat16 h = __float2bfloat16(w1);
    const size_t b = (size_t)o * K2;
    g_B2[b + c]       = h;
    g_B2[b + 256 + c] = __float2bfloat16(w1 - __bfloat162float(h));
    g_B2[b + 512 + c] = h;
    g_B2[b + 768 + c] = __float2bfloat16(W[(size_t)o * 512 + 256 + c]);
}

// ---------------- GEMM1 (proven R11/R13 structure, unchanged) ----------------
// BM=64, BN=256, BK=64, 256 thr (8 warps, 2Mx4N, warp tile 32x64), 2 CTAs/SM.
// C = bf16(adj_f32) @ fT^T; fused f32 row-sum -> inv_deg; epilogue scales and
// writes bf16 neigh into g_A2[:, 768:1024].  A: 2-stage LDG->cvt->STS,
// B: 3-stage cp.async, per-tile commit groups, wait_group<1>.
static constexpr int BN = 256, BK = 64;
static constexpr int BBYTES = BN * BK * 2;                   // 32 KB / stage
static constexpr int BMm = 64;
static constexpr int ABYTES = BMm * BK * 2;                  // 8 KB / stage
static constexpr int ASTG = 2, BSTG = 3, PREF = 2;

__global__ void __launch_bounds__(256, 2)
gemm1(const float* __restrict__ adjF) {
    constexpr int  THREADS = 256;
    constexpr int  KT      = NN / BK;               // 256
    constexpr int  NB_T    = BBYTES / 16 / THREADS; // 8
    constexpr int  RSTRIDE = THREADS / 8;           // 32 rows per t-step
    constexpr uint32_t A_OFF = 0;
    constexpr uint32_t B_OFF = ASTG * ABYTES;

    extern __shared__ char smraw[];
    __shared__ float sdeg[BMm];
    const uint32_t sb = (smem_u32(smraw) + 127u) & ~127u;

    const int tid  = threadIdx.x;
    const int lane = tid & 31;
    const int w    = tid >> 5;
    const int wm   = w >> 2;            // 0..1  (M dir)
    const int wn   = w & 3;             // 0..3  (N dir)
    const long m0  = (long)blockIdx.x * BMm;

    float acc[2][8][4];
#pragma unroll
    for (int i = 0; i < 2; i++)
#pragma unroll
        for (int j = 0; j < 8; j++)
#pragma unroll
            for (int k = 0; k < 4; k++) acc[i][j][k] = 0.f;

    // ---- B loader state (induction) ----
    const int rowB = tid >> 3, cB = tid & 7;
    const __nv_bfloat16* pBg = g_fT + (size_t)rowB * NN + cB * 8;  // next tile
    const uint32_t offB = (uint32_t)rowB * 128u +
                          ((uint32_t)(cB ^ (rowB & 7)) << 4);
    uint32_t dstB = sb + B_OFF;                                    // stage cursor
    auto cpB = [&]() {                                             // loads next tile
#pragma unroll
        for (int t = 0; t < NB_T; t++)
            cp16(dstB + offB + (uint32_t)t * (RSTRIDE * 128u),
                 pBg + (size_t)t * RSTRIDE * NN);
        pBg  += BK;
        dstB += BBYTES;
        if (dstB == sb + B_OFF + BSTG * BBYTES) dstB = sb + B_OFF;
    };

    // ---- A staging: LDG f32 -> rowsum + packed bf16 regs -> STS ----
    uint32_t rP[8];                     // 16 bf16 (packed) = this thread's slice
    float    rowsum = 0.f;
    const int arow = tid >> 2;          // 0..63 (4 threads per row)
    const int aq   = tid & 3;           // cols aq*16 .. aq*16+15
    const float* pA1 = adjF + (m0 + arow) * (long)NN + aq * 16;    // next tile
    auto ldgA = [&]() {
#pragma unroll
        for (int j = 0; j < 4; j++) {
            float4 v = ldcs4(pA1 + j * 4);
            rowsum += (v.x + v.y) + (v.z + v.w);   // exact f32 degree
            rP[2 * j]     = packbf2(v.x, v.y);
            rP[2 * j + 1] = packbf2(v.z, v.w);
        }
        pA1 += BK;
    };
    // stsA: second chunk offset = first ^ 16 (c even -> (c+1)^rs == (c^rs)^1)
    const uint32_t sA0 = sb + A_OFF + (uint32_t)arow * 128u +
                         ((uint32_t)((aq * 2) ^ (arow & 7)) << 4);
    auto stsA = [&](int s) {
        const uint32_t a0 = sA0 + (uint32_t)s * ABYTES;
        sts128(a0,      rP[0], rP[1], rP[2], rP[3]);
        sts128(a0 ^ 16, rP[4], rP[5], rP[6], rP[7]);
    };

    // ---- ldmatrix fragment row terms (computed once) ----
    const int lhi  = lane >> 4;                       // chunk parity
    uint32_t rtA[2], rtB[4];
#pragma unroll
    for (int mi = 0; mi < 2; mi++) {
        const int row = wm * 32 + (lane & 15) + mi * 16;
        rtA[mi] = (uint32_t)row * 128u | ((uint32_t)(row & 7) << 4);
    }
#pragma unroll
    for (int nb = 0; nb < 4; nb++) {
        const int row = wn * 64 + (lane & 15) + nb * 16;
        rtB[nb] = (uint32_t)row * 128u | ((uint32_t)(row & 7) << 4);
    }

    auto compute = [&](uint32_t aBase, uint32_t bBase, int ks0, int ks1) {
#pragma unroll
        for (int ks = ks0; ks < ks1; ks++) {
            const uint32_t cx = (uint32_t)(ks * 2 + lhi) << 4;
            uint32_t af[2][4], bf[4][4];
#pragma unroll
            for (int mi = 0; mi < 2; mi++) ldsm4(af[mi], (aBase + rtA[mi]) ^ cx);
#pragma unroll
            for (int nb = 0; nb < 4; nb++) ldsm4(bf[nb], (bBase + rtB[nb]) ^ cx);
#pragma unroll
            for (int mi = 0; mi < 2; mi++)
#pragma unroll
                for (int nb = 0; nb < 4; nb++) {
                    mma16816(acc[mi][nb * 2],     af[mi], bf[nb][0], bf[nb][2]);
                    mma16816(acc[mi][nb * 2 + 1], af[mi], bf[nb][1], bf[nb][3]);
                }
        }
    };

    // ---------------- prologue ----------------
    ldgA(); stsA(0);                // tile 0 A into stage 0
    ldgA();                         // tile 1 A staged in regs (packed)
    cpB(); cp_commit();             // tile 0 B -> stage 0
    cpB(); cp_commit();             // tile 1 B -> stage 1

    // ---------------- main loop ----------------
    // Invariant at top of iter kt: committed groups = {kt, kt+1}.
    // wait<1> -> tile kt complete. Refill stage (kt+2)%3 == (kt-1)%3 was last
    // read at iter kt-1; the barrier proves all warps finished it. stsA target
    // stage (kt+1)%2 likewise. Loads issue mid-tile (between ks 0-1 and 2-3).
    uint32_t cAs = sb + A_OFF;          // compute stage cursors (tile kt)
    uint32_t cBs = sb + B_OFF;
    for (int kt = 0; kt < KT; kt++) {
        cp_wait<PREF - 1>();
        __syncthreads();
        compute(cAs, cBs, 0, 2);                    // ks 0,1 (data resident)
        if (kt + 2 < KT) cpB();
        cp_commit();                    // exactly one group per iteration
        if (kt + 1 < KT) stsA((kt + 1) & 1);        // rP holds tile kt+1
        if (kt + 2 < KT) ldgA();
        compute(cAs, cBs, 2, 4);                    // ks 2,3
        cAs += ABYTES;
        if (cAs == sb + A_OFF + ASTG * ABYTES) cAs = sb + A_OFF;
        cBs += BBYTES;
        if (cBs == sb + B_OFF + BSTG * BBYTES) cBs = sb + B_OFF;
    }

    // ---------------- epilogue: inv_deg scale, bf16 -> g_A2[:,768:1024] -----
    rowsum += __shfl_xor_sync(0xFFFFFFFFu, rowsum, 1);
    rowsum += __shfl_xor_sync(0xFFFFFFFFu, rowsum, 2);
    if ((tid & 3) == 0) sdeg[tid >> 2] = 1.0f / (rowsum + 1.0f);
    __syncthreads();

#pragma unroll
    for (int mi = 0; mi < 2; mi++) {
        const int rl = wm * 32 + mi * 16 + (lane >> 2);
        const float slo = sdeg[rl];
        const float shi = sdeg[rl + 8];
        const long glo = m0 + rl, ghi = glo + 8;
#pragma unroll
        for (int ni = 0; ni < 8; ni++) {
            const int col = wn * 64 + ni * 8 + (lane & 3) * 2;
            const float* a = acc[mi][ni];
            *reinterpret_cast<uint32_t*>(g_A2 + glo * K2 + 768 + col) =
                packbf2(a[0] * slo, a[1] * slo);
            *reinterpret_cast<uint32_t*>(g_A2 + ghi * K2 + 768 + col) =
                packbf2(a[2] * shi, a[3] * shi);
        }
    }
}

// ---------------- GEMM2: out = A2 @ B2^T (K=1024 hi/lo split) ---------------
// BM=128, BN=128, 256 thr (8 warps, 4Mx2N, warp tile 32x64), 2 CTAs/SM,
// grid (128, 2) = 256 CTAs (full SM coverage).  Both operands 3-stage
// cp.async (16 KB each/stage, 96 KB smem), PREF=2, wait_group<1>.
static constexpr int G2_TILE = 128 * BK * 2;                 // 16 KB

__global__ void __launch_bounds__(256, 2)
gemm2(float* __restrict__ outF) {
    constexpr int  KT    = K2 / BK;                 // 16
    constexpr uint32_t A_OFF = 0;
    constexpr uint32_t B_OFF = 3 * G2_TILE;

    extern __shared__ char smraw[];
    const uint32_t sb = (smem_u32(smraw) + 127u) & ~127u;

    const int tid  = threadIdx.x;
    const int lane = tid & 31;
    const int w    = tid >> 5;
    const int wm   = w >> 1;            // 0..3  (M dir)
    const int wn   = w & 1;             // 0..1  (N dir)
    const long m0  = (long)blockIdx.x * 128;
    const long n0  = (long)blockIdx.y * 128;

    float acc[2][8][4];
#pragma unroll
    for (int i = 0; i < 2; i++)
#pragma unroll
        for (int j = 0; j < 8; j++)
#pragma unroll
            for (int k = 0; k < 4; k++) acc[i][j][k] = 0.f;

    // ---- tile loaders (A and B symmetric: 128 rows x 64 bf16 cols) ----
    const int rowL = tid >> 3, cL = tid & 7;        // 32 rows per t-step
    const uint32_t offL = (uint32_t)rowL * 128u +
                          ((uint32_t)(cL ^ (rowL & 7)) << 4);
    const __nv_bfloat16* pA = g_A2 + (m0 + rowL) * (size_t)K2 + cL * 8;
    const __nv_bfloat16* pB = g_B2 + (n0 + rowL) * (size_t)K2 + cL * 8;
    uint32_t dstA = sb + A_OFF, dstB = sb + B_OFF;
    auto cpT = [&]() {                              // loads next tile (A+B)
#pragma unroll
        for (int t = 0; t < 4; t++) {
            cp16(dstA + offL + (uint32_t)t * (32 * 128u), pA + (size_t)t * 32 * K2);
            cp16(dstB + offL + (uint32_t)t * (32 * 128u), pB + (size_t)t * 32 * K2);
        }
        pA += BK; pB += BK;
        dstA += G2_TILE; if (dstA == sb + A_OFF + 3 * G2_TILE) dstA = sb + A_OFF;
        dstB += G2_TILE; if (dstB == sb + B_OFF + 3 * G2_TILE) dstB = sb + B_OFF;
    };

    // ---- ldmatrix fragment row terms ----
    const int lhi = lane >> 4;
    uint32_t rtA[2], rtB[4];
#pragma unroll
    for (int mi = 0; mi < 2; mi++) {
        const int row = wm * 32 + (lane & 15) + mi * 16;      // 0..127
        rtA[mi] = (uint32_t)row * 128u | ((uint32_t)(row & 7) << 4);
    }
#pragma unroll
    for (int nb = 0; nb < 4; nb++) {
        const int row = wn * 64 + (lane & 15) + nb * 16;      // 0..127
        rtB[nb] = (uint32_t)row * 128u | ((uint32_t)(row & 7) << 4);
    }

    auto compute = [&](uint32_t aBase, uint32_t bBase, int ks0, int ks1) {
#pragma unroll
        for (int ks = ks0; ks < ks1; ks++) {
            const uint32_t cx = (uint32_t)(ks * 2 + lhi) << 4;
            uint32_t af[2][4], bf[4][4];
#pragma unroll
            for (int mi = 0; mi < 2; mi++) ldsm4(af[mi], (aBase + rtA[mi]) ^ cx);
#pragma unroll
            for (int nb = 0; nb < 4; nb++) ldsm4(bf[nb], (bBase + rtB[nb]) ^ cx);
#pragma unroll
            for (int mi = 0; mi < 2; mi++)
#pragma unroll
                for (int nb = 0; nb < 4; nb++) {
                    mma16816(acc[mi][nb * 2],     af[mi], bf[nb][0], bf[nb][2]);
                    mma16816(acc[mi][nb * 2 + 1], af[mi], bf[nb][1], bf[nb][3]);
                }
        }
    };

    // ---------------- prologue: tiles 0,1 in flight -------------------------
    cpT(); cp_commit();
    cpT(); cp_commit();

    // ---------------- main loop (same invariants as gemm1's B pipe) ---------
    uint32_t cAs = sb + A_OFF, cBs = sb + B_OFF;
    for (int kt = 0; kt < KT; kt++) {
        cp_wait<1>();
        __syncthreads();
        compute(cAs, cBs, 0, 2);
        if (kt + 2 < KT) cpT();
        cp_commit();
        compute(cAs, cBs, 2, 4);
        cAs += G2_TILE; if (cAs == sb + A_OFF + 3 * G2_TILE) cAs = sb + A_OFF;
        cBs += G2_TILE; if (cBs == sb + B_OFF + 3 * G2_TILE) cBs = sb + B_OFF;
    }

    // ---------------- epilogue: fp32 out ----------------
#pragma unroll
    for (int mi = 0; mi < 2; mi++) {
        const int rl = wm * 32 + mi * 16 + (lane >> 2);
        const long glo = m0 + rl, ghi = glo + 8;
#pragma unroll
        for (int ni = 0; ni < 8; ni++) {
            const long col = n0 + wn * 64 + ni * 8 + (lane & 3) * 2;
            const float* a = acc[mi][ni];
            *reinterpret_cast<float2*>(outF + glo * DF + col) =
                make_float2(a[0], a[1]);
            *reinterpret_cast<float2*>(outF + ghi * DF + col) =
                make_float2(a[2], a[3]);
        }
    }
}

static constexpr uint32_t SMEM1 = ASTG * ABYTES + BSTG * BBYTES + 128; // ~112.1 KB
static constexpr uint32_t SMEM2 = 6 * G2_TILE + 128;                   // ~96.1 KB

// ---------------- launch -----------------------------------------------------
extern "C" void kernel_launch(void* const* d_in, const int* in_sizes, int n_in,
                              void* d_out, int out_size) {
    const float* features = nullptr;
    const float* adj      = nullptr;
    const float* W        = nullptr;
    for (int i = 0; i < n_in; i++) {
        if (in_sizes[i] == NN * DF)          features = (const float*)d_in[i];
        else if (in_sizes[i] == DF * 2 * DF) W        = (const float*)d_in[i];
        else                                  adj      = (const float*)d_in[i];
    }

    cudaFuncSetAttribute(gemm1, cudaFuncAttributeMaxDynamicSharedMemorySize, SMEM1);
    cudaFuncSetAttribute(gemm2, cudaFuncAttributeMaxDynamicSharedMemorySize, SMEM2);

    prep_fT<<<dim3(NN / 32, DF / 32), dim3(32, 8)>>>(features);
    prep_A2<<<NN, 256>>>(features);
    prep_W<<<DF, 256>>>(W);
    gemm1<<<NN / BMm, 256, SMEM1>>>(adj);
    gemm2<<<dim3(NN / 128, 2), 256, SMEM2>>>((float*)d_out);
}

// round 15
// speedup vs baseline: 1.0590x; 1.0135x over previous
#include <cuda_runtime.h>
#include <cuda_bf16.h>
#include <cstdint>

#define DEVINL __device__ __forceinline__

static constexpr int NN = 16384;   // nodes
static constexpr int DF = 256;     // feature dim == out dim
static constexpr int K2 = 1024;    // GEMM2 K: [f_hi | f_hi | f_lo | neigh]

// ---------------- scratch (device globals; no allocation allowed) -----------
__device__ __align__(128) __nv_bfloat16 g_fT[(size_t)DF * NN];   // 8 MB  features^T bf16
__device__ __align__(128) __nv_bfloat16 g_A2[(size_t)NN * K2];   // 32 MB GEMM2 A operand
__device__ __align__(128) __nv_bfloat16 g_B2[(size_t)DF * K2];   // 512 KB GEMM2 B operand

// ---------------- PTX helpers (all legal at compute_103 virtual arch) -------
DEVINL uint32_t smem_u32(const void* p) {
    uint32_t a;
    asm("{ .reg .u64 t; cvta.to.shared.u64 t, %1; cvt.u32.u64 %0, t; }"
        : "=r"(a) : "l"(p));
    return a;
}
DEVINL void cp16(uint32_t dst, const void* src) {
    asm volatile("cp.async.cg.shared.global [%0], [%1], 16;"
                 :: "r"(dst), "l"(src) : "memory");
}
DEVINL void cp_commit() { asm volatile("cp.async.commit_group;" ::: "memory"); }
template <int N> DEVINL void cp_wait() {
    asm volatile("cp.async.wait_group %0;" :: "n"(N) : "memory");
}
DEVINL void ldsm4(uint32_t* r, uint32_t a) {
    asm volatile("ldmatrix.sync.aligned.m8n8.x4.shared.b16 {%0,%1,%2,%3}, [%4];"
                 : "=r"(r[0]), "=r"(r[1]), "=r"(r[2]), "=r"(r[3]) : "r"(a));
}
DEVINL void sts128(uint32_t a, uint32_t x, uint32_t y, uint32_t z, uint32_t w) {
    asm volatile("st.shared.v4.b32 [%0], {%1,%2,%3,%4};"
                 :: "r"(a), "r"(x), "r"(y), "r"(z), "r"(w));
}
DEVINL void mma16816(float* d, const uint32_t* a, uint32_t b0, uint32_t b1) {
    asm volatile(
        "mma.sync.aligned.m16n8k16.row.col.f32.bf16.bf16.f32 "
        "{%0,%1,%2,%3}, {%4,%5,%6,%7}, {%8,%9}, {%0,%1,%2,%3};"
        : "+f"(d[0]), "+f"(d[1]), "+f"(d[2]), "+f"(d[3])
        : "r"(a[0]), "r"(a[1]), "r"(a[2]), "r"(a[3]), "r"(b0), "r"(b1));
}
DEVINL uint32_t packbf2(float x, float y) {
    __nv_bfloat162 h = __floats2bfloat162_rn(x, y);
    return *reinterpret_cast<uint32_t*>(&h);
}
DEVINL float4 ldcs4(const float* p) {
    float4 v;
    asm volatile("ld.global.cs.v4.f32 {%0,%1,%2,%3}, [%4];"
                 : "=f"(v.x), "=f"(v.y), "=f"(v.z), "=f"(v.w) : "l"(p));
    return v;
}

// ---------------- prep kernels ----------------------------------------------

// Fused features prep: one pass over f writes
//   g_fT  (features^T bf16, for GEMM1 B operand) and
//   g_A2[:, 0:768] = [f_hi | f_hi | f_lo]  (GEMM2 A operand, f parts).
// grid(512, 8), block(32, 8); 32x32 tile per block.
__global__ void prep_fused(const float* __restrict__ f) {
    __shared__ __nv_bfloat16 tile[32][33];
    const int i0 = blockIdx.x * 32, d0 = blockIdx.y * 32;
    const int tx = threadIdx.x, ty = threadIdx.y;
#pragma unroll
    for (int k = 0; k < 32; k += 8) {
        const int i = i0 + ty + k, d = d0 + tx;
        const float v = f[(size_t)i * DF + d];
        const __nv_bfloat16 h = __float2bfloat16(v);
        tile[ty + k][tx] = h;
        const size_t b = (size_t)i * K2;
        g_A2[b + d]       = h;
        g_A2[b + 256 + d] = h;
        g_A2[b + 512 + d] = __float2bfloat16(v - __bfloat162float(h));
    }
    __syncthreads();
#pragma unroll
    for (int k = 0; k < 32; k += 8)
        g_fT[(size_t)(d0 + ty + k) * NN + i0 + tx] = tile[tx][ty + k];
}

// B2 = [W1_hi | W1_lo | W1_hi | W2]
__global__ void __launch_bounds__(256) prep_W(const float* __restrict__ W) {
    const int o = blockIdx.x, c = threadIdx.x;
    const float w1 = W[(size_t)o * 512 + c];
    const __nv_bfloat16 h = __float2bfloat16(w1);
    const size_t b = (size_t)o * K2;
    g_B2[b + c]       = h;
    g_B2[b + 256 + c] = __float2bfloat16(w1 - __bfloat162float(h));
    g_B2[b + 512 + c] = h;
    g_B2[b + 768 + c] = __float2bfloat16(W[(size_t)o * 512 + 256 + c]);
}

// ---------------- GEMM1 (proven R11/R13/R14 structure, unchanged) ------------
// BM=64, BN=256, BK=64, 256 thr (8 warps, 2Mx4N, warp tile 32x64), 2 CTAs/SM.
// C = bf16(adj_f32) @ fT^T; fused f32 row-sum -> inv_deg; epilogue scales and
// writes bf16 neigh into g_A2[:, 768:1024].  A: 2-stage LDG->cvt->STS,
// B: 3-stage cp.async, per-tile commit groups, wait_group<1>.
static constexpr int BN = 256, BK = 64;
static constexpr int BBYTES = BN * BK * 2;                   // 32 KB / stage
static constexpr int BMm = 64;
static constexpr int ABYTES = BMm * BK * 2;                  // 8 KB / stage
static constexpr int ASTG = 2, BSTG = 3, PREF = 2;

__global__ void __launch_bounds__(256, 2)
gemm1(const float* __restrict__ adjF) {
    constexpr int  THREADS = 256;
    constexpr int  KT      = NN / BK;               // 256
    constexpr int  NB_T    = BBYTES / 16 / THREADS; // 8
    constexpr int  RSTRIDE = THREADS / 8;           // 32 rows per t-step
    constexpr uint32_t A_OFF = 0;
    constexpr uint32_t B_OFF = ASTG * ABYTES;

    extern __shared__ char smraw[];
    __shared__ float sdeg[BMm];
    const uint32_t sb = (smem_u32(smraw) + 127u) & ~127u;

    const int tid  = threadIdx.x;
    const int lane = tid & 31;
    const int w    = tid >> 5;
    const int wm   = w >> 2;            // 0..1  (M dir)
    const int wn   = w & 3;             // 0..3  (N dir)
    const long m0  = (long)blockIdx.x * BMm;

    float acc[2][8][4];
#pragma unroll
    for (int i = 0; i < 2; i++)
#pragma unroll
        for (int j = 0; j < 8; j++)
#pragma unroll
            for (int k = 0; k < 4; k++) acc[i][j][k] = 0.f;

    // ---- B loader state (induction) ----
    const int rowB = tid >> 3, cB = tid & 7;
    const __nv_bfloat16* pBg = g_fT + (size_t)rowB * NN + cB * 8;  // next tile
    const uint32_t offB = (uint32_t)rowB * 128u +
                          ((uint32_t)(cB ^ (rowB & 7)) << 4);
    uint32_t dstB = sb + B_OFF;                                    // stage cursor
    auto cpB = [&]() {                                             // loads next tile
#pragma unroll
        for (int t = 0; t < NB_T; t++)
            cp16(dstB + offB + (uint32_t)t * (RSTRIDE * 128u),
                 pBg + (size_t)t * RSTRIDE * NN);
        pBg  += BK;
        dstB += BBYTES;
        if (dstB == sb + B_OFF + BSTG * BBYTES) dstB = sb + B_OFF;
    };

    // ---- A staging: LDG f32 -> rowsum + packed bf16 regs -> STS ----
    uint32_t rP[8];                     // 16 bf16 (packed) = this thread's slice
    float    rowsum = 0.f;
    const int arow = tid >> 2;          // 0..63 (4 threads per row)
    const int aq   = tid & 3;           // cols aq*16 .. aq*16+15
    const float* pA1 = adjF + (m0 + arow) * (long)NN + aq * 16;    // next tile
    auto ldgA = [&]() {
#pragma unroll
        for (int j = 0; j < 4; j++) {
            float4 v = ldcs4(pA1 + j * 4);
            rowsum += (v.x + v.y) + (v.z + v.w);   // exact f32 degree
            rP[2 * j]     = packbf2(v.x, v.y);
            rP[2 * j + 1] = packbf2(v.z, v.w);
        }
        pA1 += BK;
    };
    // stsA: second chunk offset = first ^ 16 (c even -> (c+1)^rs == (c^rs)^1)
    const uint32_t sA0 = sb + A_OFF + (uint32_t)arow * 128u +
                         ((uint32_t)((aq * 2) ^ (arow & 7)) << 4);
    auto stsA = [&](int s) {
        const uint32_t a0 = sA0 + (uint32_t)s * ABYTES;
        sts128(a0,      rP[0], rP[1], rP[2], rP[3]);
        sts128(a0 ^ 16, rP[4], rP[5], rP[6], rP[7]);
    };

    // ---- ldmatrix fragment row terms (computed once) ----
    const int lhi  = lane >> 4;                       // chunk parity
    uint32_t rtA[2], rtB[4];
#pragma unroll
    for (int mi = 0; mi < 2; mi++) {
        const int row = wm * 32 + (lane & 15) + mi * 16;
        rtA[mi] = (uint32_t)row * 128u | ((uint32_t)(row & 7) << 4);
    }
#pragma unroll
    for (int nb = 0; nb < 4; nb++) {
        const int row = wn * 64 + (lane & 15) + nb * 16;
        rtB[nb] = (uint32_t)row * 128u | ((uint32_t)(row & 7) << 4);
    }

    auto compute = [&](uint32_t aBase, uint32_t bBase, int ks0, int ks1) {
#pragma unroll
        for (int ks = ks0; ks < ks1; ks++) {
            const uint32_t cx = (uint32_t)(ks * 2 + lhi) << 4;
            uint32_t af[2][4], bf[4][4];
#pragma unroll
            for (int mi = 0; mi < 2; mi++) ldsm4(af[mi], (aBase + rtA[mi]) ^ cx);
#pragma unroll
            for (int nb = 0; nb < 4; nb++) ldsm4(bf[nb], (bBase + rtB[nb]) ^ cx);
#pragma unroll
            for (int mi = 0; mi < 2; mi++)
#pragma unroll
                for (int nb = 0; nb < 4; nb++) {
                    mma16816(acc[mi][nb * 2],     af[mi], bf[nb][0], bf[nb][2]);
                    mma16816(acc[mi][nb * 2 + 1], af[mi], bf[nb][1], bf[nb][3]);
                }
        }
    };

    // ---------------- prologue ----------------
    ldgA(); stsA(0);                // tile 0 A into stage 0
    ldgA();                         // tile 1 A staged in regs (packed)
    cpB(); cp_commit();             // tile 0 B -> stage 0
    cpB(); cp_commit();             // tile 1 B -> stage 1

    // ---------------- main loop ----------------
    // Invariant at top of iter kt: committed groups = {kt, kt+1}.
    // wait<1> -> tile kt complete. Refill stage (kt+2)%3 == (kt-1)%3 was last
    // read at iter kt-1; the barrier proves all warps finished it. stsA target
    // stage (kt+1)%2 likewise. Loads issue mid-tile (between ks 0-1 and 2-3).
    uint32_t cAs = sb + A_OFF;          // compute stage cursors (tile kt)
    uint32_t cBs = sb + B_OFF;
    for (int kt = 0; kt < KT; kt++) {
        cp_wait<PREF - 1>();
        __syncthreads();
        compute(cAs, cBs, 0, 2);                    // ks 0,1 (data resident)
        if (kt + 2 < KT) cpB();
        cp_commit();                    // exactly one group per iteration
        if (kt + 1 < KT) stsA((kt + 1) & 1);        // rP holds tile kt+1
        if (kt + 2 < KT) ldgA();
        compute(cAs, cBs, 2, 4);                    // ks 2,3
        cAs += ABYTES;
        if (cAs == sb + A_OFF + ASTG * ABYTES) cAs = sb + A_OFF;
        cBs += BBYTES;
        if (cBs == sb + B_OFF + BSTG * BBYTES) cBs = sb + B_OFF;
    }

    // ---------------- epilogue: inv_deg scale, bf16 -> g_A2[:,768:1024] -----
    rowsum += __shfl_xor_sync(0xFFFFFFFFu, rowsum, 1);
    rowsum += __shfl_xor_sync(0xFFFFFFFFu, rowsum, 2);
    if ((tid & 3) == 0) sdeg[tid >> 2] = 1.0f / (rowsum + 1.0f);
    __syncthreads();

#pragma unroll
    for (int mi = 0; mi < 2; mi++) {
        const int rl = wm * 32 + mi * 16 + (lane >> 2);
        const float slo = sdeg[rl];
        const float shi = sdeg[rl + 8];
        const long glo = m0 + rl, ghi = glo + 8;
#pragma unroll
        for (int ni = 0; ni < 8; ni++) {
            const int col = wn * 64 + ni * 8 + (lane & 3) * 2;
            const float* a = acc[mi][ni];
            *reinterpret_cast<uint32_t*>(g_A2 + glo * K2 + 768 + col) =
                packbf2(a[0] * slo, a[1] * slo);
            *reinterpret_cast<uint32_t*>(g_A2 + ghi * K2 + 768 + col) =
                packbf2(a[2] * shi, a[3] * shi);
        }
    }
}

// ---------------- GEMM2: out = A2 @ B2^T (K=1024 hi/lo split) ---------------
// BM=128, BN=128, 256 thr (8 warps, 4Mx2N, warp tile 32x64), 2 CTAs/SM,
// grid (128, 2) = 256 CTAs (full SM coverage).  Both operands 3-stage
// cp.async (16 KB each/stage, 96 KB smem), PREF=2, wait_group<1>.
static constexpr int G2_TILE = 128 * BK * 2;                 // 16 KB

__global__ void __launch_bounds__(256, 2)
gemm2(float* __restrict__ outF) {
    constexpr int  KT    = K2 / BK;                 // 16
    constexpr uint32_t A_OFF = 0;
    constexpr uint32_t B_OFF = 3 * G2_TILE;

    extern __shared__ char smraw[];
    const uint32_t sb = (smem_u32(smraw) + 127u) & ~127u;

    const int tid  = threadIdx.x;
    const int lane = tid & 31;
    const int w    = tid >> 5;
    const int wm   = w >> 1;            // 0..3  (M dir)
    const int wn   = w & 1;             // 0..1  (N dir)
    const long m0  = (long)blockIdx.x * 128;
    const long n0  = (long)blockIdx.y * 128;

    float acc[2][8][4];
#pragma unroll
    for (int i = 0; i < 2; i++)
#pragma unroll
        for (int j = 0; j < 8; j++)
#pragma unroll
            for (int k = 0; k < 4; k++) acc[i][j][k] = 0.f;

    // ---- tile loaders (A and B symmetric: 128 rows x 64 bf16 cols) ----
    const int rowL = tid >> 3, cL = tid & 7;        // 32 rows per t-step
    const uint32_t offL = (uint32_t)rowL * 128u +
                          ((uint32_t)(cL ^ (rowL & 7)) << 4);
    const __nv_bfloat16* pA = g_A2 + (m0 + rowL) * (size_t)K2 + cL * 8;
    const __nv_bfloat16* pB = g_B2 + (n0 + rowL) * (size_t)K2 + cL * 8;
    uint32_t dstA = sb + A_OFF, dstB = sb + B_OFF;
    auto cpT = [&]() {                              // loads next tile (A+B)
#pragma unroll
        for (int t = 0; t < 4; t++) {
            cp16(dstA + offL + (uint32_t)t * (32 * 128u), pA + (size_t)t * 32 * K2);
            cp16(dstB + offL + (uint32_t)t * (32 * 128u), pB + (size_t)t * 32 * K2);
        }
        pA += BK; pB += BK;
        dstA += G2_TILE; if (dstA == sb + A_OFF + 3 * G2_TILE) dstA = sb + A_OFF;
        dstB += G2_TILE; if (dstB == sb + B_OFF + 3 * G2_TILE) dstB = sb + B_OFF;
    };

    // ---- ldmatrix fragment row terms ----
    const int lhi = lane >> 4;
    uint32_t rtA[2], rtB[4];
#pragma unroll
    for (int mi = 0; mi < 2; mi++) {
        const int row = wm * 32 + (lane & 15) + mi * 16;      // 0..127
        rtA[mi] = (uint32_t)row * 128u | ((uint32_t)(row & 7) << 4);
    }
#pragma unroll
    for (int nb = 0; nb < 4; nb++) {
        const int row = wn * 64 + (lane & 15) + nb * 16;      // 0..127
        rtB[nb] = (uint32_t)row * 128u | ((uint32_t)(row & 7) << 4);
    }

    auto compute = [&](uint32_t aBase, uint32_t bBase, int ks0, int ks1) {
#pragma unroll
        for (int ks = ks0; ks < ks1; ks++) {
            const uint32_t cx = (uint32_t)(ks * 2 + lhi) << 4;
            uint32_t af[2][4], bf[4][4];
#pragma unroll
            for (int mi = 0; mi < 2; mi++) ldsm4(af[mi], (aBase + rtA[mi]) ^ cx);
#pragma unroll
            for (int nb = 0; nb < 4; nb++) ldsm4(bf[nb], (bBase + rtB[nb]) ^ cx);
#pragma unroll
            for (int mi = 0; mi < 2; mi++)
#pragma unroll
                for (int nb = 0; nb < 4; nb++) {
                    mma16816(acc[mi][nb * 2],     af[mi], bf[nb][0], bf[nb][2]);
                    mma16816(acc[mi][nb * 2 + 1], af[mi], bf[nb][1], bf[nb][3]);
                }
        }
    };

    // ---------------- prologue: tiles 0,1 in flight -------------------------
    cpT(); cp_commit();
    cpT(); cp_commit();

    // ---------------- main loop (same invariants as gemm1's B pipe) ---------
    uint32_t cAs = sb + A_OFF, cBs = sb + B_OFF;
    for (int kt = 0; kt < KT; kt++) {
        cp_wait<1>();
        __syncthreads();
        compute(cAs, cBs, 0, 2);
        if (kt + 2 < KT) cpT();
        cp_commit();
        compute(cAs, cBs, 2, 4);
        cAs += G2_TILE; if (cAs == sb + A_OFF + 3 * G2_TILE) cAs = sb + A_OFF;
        cBs += G2_TILE; if (cBs == sb + B_OFF + 3 * G2_TILE) cBs = sb + B_OFF;
    }

    // ---------------- epilogue: fp32 out ----------------
#pragma unroll
    for (int mi = 0; mi < 2; mi++) {
        const int rl = wm * 32 + mi * 16 + (lane >> 2);
        const long glo = m0 + rl, ghi = glo + 8;
#pragma unroll
        for (int ni = 0; ni < 8; ni++) {
            const long col = n0 + wn * 64 + ni * 8 + (lane & 3) * 2;
            const float* a = acc[mi][ni];
            *reinterpret_cast<float2*>(outF + glo * DF + col) =
                make_float2(a[0], a[1]);
            *reinterpret_cast<float2*>(outF + ghi * DF + col) =
                make_float2(a[2], a[3]);
        }
    }
}

static constexpr uint32_t SMEM1 = ASTG * ABYTES + BSTG * BBYTES + 128; // ~112.1 KB
static constexpr uint32_t SMEM2 = 6 * G2_TILE + 128;                   // ~96.1 KB

// ---------------- launch -----------------------------------------------------
extern "C" void kernel_launch(void* const* d_in, const int* in_sizes, int n_in,
                              void* d_out, int out_size) {
    const float* features = nullptr;
    const float* adj      = nullptr;
    const float* W        = nullptr;
    for (int i = 0; i < n_in; i++) {
        if (in_sizes[i] == NN * DF)          features = (const float*)d_in[i];
        else if (in_sizes[i] == DF * 2 * DF) W        = (const float*)d_in[i];
        else                                  adj      = (const float*)d_in[i];
    }

    cudaFuncSetAttribute(gemm1, cudaFuncAttributeMaxDynamicSharedMemorySize, SMEM1);
    cudaFuncSetAttribute(gemm2, cudaFuncAttributeMaxDynamicSharedMemorySize, SMEM2);

    prep_fused<<<dim3(NN / 32, DF / 32), dim3(32, 8)>>>(features);
    prep_W<<<DF, 256>>>(W);
    gemm1<<<NN / BMm, 256, SMEM1>>>(adj);
    gemm2<<<dim3(NN / 128, 2), 256, SMEM2>>>((float*)d_out);
}

// round 16
// speedup vs baseline: 1.0823x; 1.0220x over previous
#include <cuda_runtime.h>
#include <cuda_bf16.h>
#include <cstdint>

#define DEVINL __device__ __forceinline__

static constexpr int NN = 16384;   // nodes
static constexpr int DF = 256;     // feature dim == out dim
static constexpr int K2 = 1024;    // GEMM2 K: [f_hi | f_hi | f_lo | neigh]

// ---------------- scratch (device globals; no allocation allowed) -----------
__device__ __align__(128) __nv_bfloat16 g_fT[(size_t)DF * NN];   // 8 MB  features^T bf16
__device__ __align__(128) __nv_bfloat16 g_A2[(size_t)NN * K2];   // 32 MB GEMM2 A operand
__device__ __align__(128) __nv_bfloat16 g_B2[(size_t)DF * K2];   // 512 KB GEMM2 B operand

// ---------------- PTX helpers (all legal at compute_103 virtual arch) -------
DEVINL uint32_t smem_u32(const void* p) {
    uint32_t a;
    asm("{ .reg .u64 t; cvta.to.shared.u64 t, %1; cvt.u32.u64 %0, t; }"
        : "=r"(a) : "l"(p));
    return a;
}
DEVINL void cp16(uint32_t dst, const void* src) {
    asm volatile("cp.async.cg.shared.global [%0], [%1], 16;"
                 :: "r"(dst), "l"(src) : "memory");
}
DEVINL void cp_commit() { asm volatile("cp.async.commit_group;" ::: "memory"); }
template <int N> DEVINL void cp_wait() {
    asm volatile("cp.async.wait_group %0;" :: "n"(N) : "memory");
}
DEVINL void ldsm4(uint32_t* r, uint32_t a) {
    asm volatile("ldmatrix.sync.aligned.m8n8.x4.shared.b16 {%0,%1,%2,%3}, [%4];"
                 : "=r"(r[0]), "=r"(r[1]), "=r"(r[2]), "=r"(r[3]) : "r"(a));
}
DEVINL void sts128(uint32_t a, uint32_t x, uint32_t y, uint32_t z, uint32_t w) {
    asm volatile("st.shared.v4.b32 [%0], {%1,%2,%3,%4};"
                 :: "r"(a), "r"(x), "r"(y), "r"(z), "r"(w));
}
DEVINL void mma16816(float* d, const uint32_t* a, uint32_t b0, uint32_t b1) {
    asm volatile(
        "mma.sync.aligned.m16n8k16.row.col.f32.bf16.bf16.f32 "
        "{%0,%1,%2,%3}, {%4,%5,%6,%7}, {%8,%9}, {%0,%1,%2,%3};"
        : "+f"(d[0]), "+f"(d[1]), "+f"(d[2]), "+f"(d[3])
        : "r"(a[0]), "r"(a[1]), "r"(a[2]), "r"(a[3]), "r"(b0), "r"(b1));
}
DEVINL uint32_t packbf2(float x, float y) {
    __nv_bfloat162 h = __floats2bfloat162_rn(x, y);
    return *reinterpret_cast<uint32_t*>(&h);
}
DEVINL float4 ldcs4(const float* p) {
    float4 v;
    asm volatile("ld.global.cs.v4.f32 {%0,%1,%2,%3}, [%4];"
                 : "=f"(v.x), "=f"(v.y), "=f"(v.z), "=f"(v.w) : "l"(p));
    return v;
}
// PDL: signal that dependent (PDL-attributed) kernels may begin launching.
DEVINL void pdl_trigger() {
    asm volatile("griddepcontrol.launch_dependents;" ::: "memory");
}

// ---------------- prep kernels ----------------------------------------------

// Fused features prep: one pass over f writes
//   g_fT  (features^T bf16, for GEMM1 B operand) and
//   g_A2[:, 0:768] = [f_hi | f_hi | f_lo]  (GEMM2 A operand, f parts).
// grid(512, 8), block(32, 8); 32x32 tile per block.
__global__ void prep_fused(const float* __restrict__ f) {
    __shared__ __nv_bfloat16 tile[32][33];
    const int i0 = blockIdx.x * 32, d0 = blockIdx.y * 32;
    const int tx = threadIdx.x, ty = threadIdx.y;
#pragma unroll
    for (int k = 0; k < 32; k += 8) {
        const int i = i0 + ty + k, d = d0 + tx;
        const float v = f[(size_t)i * DF + d];
        const __nv_bfloat16 h = __float2bfloat16(v);
        tile[ty + k][tx] = h;
        const size_t b = (size_t)i * K2;
        g_A2[b + d]       = h;
        g_A2[b + 256 + d] = h;
        g_A2[b + 512 + d] = __float2bfloat16(v - __bfloat162float(h));
    }
    __syncthreads();
#pragma unroll
    for (int k = 0; k < 32; k += 8)
        g_fT[(size_t)(d0 + ty + k) * NN + i0 + tx] = tile[tx][ty + k];
}

// B2 = [W1_hi | W1_lo | W1_hi | W2]
__global__ void __launch_bounds__(256) prep_W(const float* __restrict__ W) {
    const int o = blockIdx.x, c = threadIdx.x;
    const float w1 = W[(size_t)o * 512 + c];
    const __nv_bfloat16 h = __float2bfloat16(w1);
    const size_t b = (size_t)o * K2;
    g_B2[b + c]       = h;
    g_B2[b + 256 + c] = __float2bfloat16(w1 - __bfloat162float(h));
    g_B2[b + 512 + c] = h;
    g_B2[b + 768 + c] = __float2bfloat16(W[(size_t)o * 512 + 256 + c]);
}

// ---------------- GEMM1 (proven R11/R13/R14 structure, unchanged) ------------
// BM=64, BN=256, BK=64, 256 thr (8 warps, 2Mx4N, warp tile 32x64), 2 CTAs/SM.
// C = bf16(adj_f32) @ fT^T; fused f32 row-sum -> inv_deg; epilogue scales and
// writes bf16 neigh into g_A2[:, 768:1024].  A: 2-stage LDG->cvt->STS,
// B: 3-stage cp.async, per-tile commit groups, wait_group<1>.
// Calls pdl_trigger() at start so the PDL-attributed gemm2a can tail-fill.
static constexpr int BN = 256, BK = 64;
static constexpr int BBYTES = BN * BK * 2;                   // 32 KB / stage
static constexpr int BMm = 64;
static constexpr int ABYTES = BMm * BK * 2;                  // 8 KB / stage
static constexpr int ASTG = 2, BSTG = 3, PREF = 2;

__global__ void __launch_bounds__(256, 2)
gemm1(const float* __restrict__ adjF) {
    constexpr int  THREADS = 256;
    constexpr int  KT      = NN / BK;               // 256
    constexpr int  NB_T    = BBYTES / 16 / THREADS; // 8
    constexpr int  RSTRIDE = THREADS / 8;           // 32 rows per t-step
    constexpr uint32_t A_OFF = 0;
    constexpr uint32_t B_OFF = ASTG * ABYTES;

    pdl_trigger();                      // allow gemm2a to start scheduling

    extern __shared__ char smraw[];
    __shared__ float sdeg[BMm];
    const uint32_t sb = (smem_u32(smraw) + 127u) & ~127u;

    const int tid  = threadIdx.x;
    const int lane = tid & 31;
    const int w    = tid >> 5;
    const int wm   = w >> 2;            // 0..1  (M dir)
    const int wn   = w & 3;             // 0..3  (N dir)
    const long m0  = (long)blockIdx.x * BMm;

    float acc[2][8][4];
#pragma unroll
    for (int i = 0; i < 2; i++)
#pragma unroll
        for (int j = 0; j < 8; j++)
#pragma unroll
            for (int k = 0; k < 4; k++) acc[i][j][k] = 0.f;

    // ---- B loader state (induction) ----
    const int rowB = tid >> 3, cB = tid & 7;
    const __nv_bfloat16* pBg = g_fT + (size_t)rowB * NN + cB * 8;  // next tile
    const uint32_t offB = (uint32_t)rowB * 128u +
                          ((uint32_t)(cB ^ (rowB & 7)) << 4);
    uint32_t dstB = sb + B_OFF;                                    // stage cursor
    auto cpB = [&]() {                                             // loads next tile
#pragma unroll
        for (int t = 0; t < NB_T; t++)
            cp16(dstB + offB + (uint32_t)t * (RSTRIDE * 128u),
                 pBg + (size_t)t * RSTRIDE * NN);
        pBg  += BK;
        dstB += BBYTES;
        if (dstB == sb + B_OFF + BSTG * BBYTES) dstB = sb + B_OFF;
    };

    // ---- A staging: LDG f32 -> rowsum + packed bf16 regs -> STS ----
    uint32_t rP[8];                     // 16 bf16 (packed) = this thread's slice
    float    rowsum = 0.f;
    const int arow = tid >> 2;          // 0..63 (4 threads per row)
    const int aq   = tid & 3;           // cols aq*16 .. aq*16+15
    const float* pA1 = adjF + (m0 + arow) * (long)NN + aq * 16;    // next tile
    auto ldgA = [&]() {
#pragma unroll
        for (int j = 0; j < 4; j++) {
            float4 v = ldcs4(pA1 + j * 4);
            rowsum += (v.x + v.y) + (v.z + v.w);   // exact f32 degree
            rP[2 * j]     = packbf2(v.x, v.y);
            rP[2 * j + 1] = packbf2(v.z, v.w);
        }
        pA1 += BK;
    };
    // stsA: second chunk offset = first ^ 16 (c even -> (c+1)^rs == (c^rs)^1)
    const uint32_t sA0 = sb + A_OFF + (uint32_t)arow * 128u +
                         ((uint32_t)((aq * 2) ^ (arow & 7)) << 4);
    auto stsA = [&](int s) {
        const uint32_t a0 = sA0 + (uint32_t)s * ABYTES;
        sts128(a0,      rP[0], rP[1], rP[2], rP[3]);
        sts128(a0 ^ 16, rP[4], rP[5], rP[6], rP[7]);
    };

    // ---- ldmatrix fragment row terms (computed once) ----
    const int lhi  = lane >> 4;                       // chunk parity
    uint32_t rtA[2], rtB[4];
#pragma unroll
    for (int mi = 0; mi < 2; mi++) {
        const int row = wm * 32 + (lane & 15) + mi * 16;
        rtA[mi] = (uint32_t)row * 128u | ((uint32_t)(row & 7) << 4);
    }
#pragma unroll
    for (int nb = 0; nb < 4; nb++) {
        const int row = wn * 64 + (lane & 15) + nb * 16;
        rtB[nb] = (uint32_t)row * 128u | ((uint32_t)(row & 7) << 4);
    }

    auto compute = [&](uint32_t aBase, uint32_t bBase, int ks0, int ks1) {
#pragma unroll
        for (int ks = ks0; ks < ks1; ks++) {
            const uint32_t cx = (uint32_t)(ks * 2 + lhi) << 4;
            uint32_t af[2][4], bf[4][4];
#pragma unroll
            for (int mi = 0; mi < 2; mi++) ldsm4(af[mi], (aBase + rtA[mi]) ^ cx);
#pragma unroll
            for (int nb = 0; nb < 4; nb++) ldsm4(bf[nb], (bBase + rtB[nb]) ^ cx);
#pragma unroll
            for (int mi = 0; mi < 2; mi++)
#pragma unroll
                for (int nb = 0; nb < 4; nb++) {
                    mma16816(acc[mi][nb * 2],     af[mi], bf[nb][0], bf[nb][2]);
                    mma16816(acc[mi][nb * 2 + 1], af[mi], bf[nb][1], bf[nb][3]);
                }
        }
    };

    // ---------------- prologue ----------------
    ldgA(); stsA(0);                // tile 0 A into stage 0
    ldgA();                         // tile 1 A staged in regs (packed)
    cpB(); cp_commit();             // tile 0 B -> stage 0
    cpB(); cp_commit();             // tile 1 B -> stage 1

    // ---------------- main loop ----------------
    // Invariant at top of iter kt: committed groups = {kt, kt+1}.
    // wait<1> -> tile kt complete. Refill stage (kt+2)%3 == (kt-1)%3 was last
    // read at iter kt-1; the barrier proves all warps finished it. stsA target
    // stage (kt+1)%2 likewise. Loads issue mid-tile (between ks 0-1 and 2-3).
    uint32_t cAs = sb + A_OFF;          // compute stage cursors (tile kt)
    uint32_t cBs = sb + B_OFF;
    for (int kt = 0; kt < KT; kt++) {
        cp_wait<PREF - 1>();
        __syncthreads();
        compute(cAs, cBs, 0, 2);                    // ks 0,1 (data resident)
        if (kt + 2 < KT) cpB();
        cp_commit();                    // exactly one group per iteration
        if (kt + 1 < KT) stsA((kt + 1) & 1);        // rP holds tile kt+1
        if (kt + 2 < KT) ldgA();
        compute(cAs, cBs, 2, 4);                    // ks 2,3
        cAs += ABYTES;
        if (cAs == sb + A_OFF + ASTG * ABYTES) cAs = sb + A_OFF;
        cBs += BBYTES;
        if (cBs == sb + B_OFF + BSTG * BBYTES) cBs = sb + B_OFF;
    }

    // ---------------- epilogue: inv_deg scale, bf16 -> g_A2[:,768:1024] -----
    rowsum += __shfl_xor_sync(0xFFFFFFFFu, rowsum, 1);
    rowsum += __shfl_xor_sync(0xFFFFFFFFu, rowsum, 2);
    if ((tid & 3) == 0) sdeg[tid >> 2] = 1.0f / (rowsum + 1.0f);
    __syncthreads();

#pragma unroll
    for (int mi = 0; mi < 2; mi++) {
        const int rl = wm * 32 + mi * 16 + (lane >> 2);
        const float slo = sdeg[rl];
        const float shi = sdeg[rl + 8];
        const long glo = m0 + rl, ghi = glo + 8;
#pragma unroll
        for (int ni = 0; ni < 8; ni++) {
            const int col = wn * 64 + ni * 8 + (lane & 3) * 2;
            const float* a = acc[mi][ni];
            *reinterpret_cast<uint32_t*>(g_A2 + glo * K2 + 768 + col) =
                packbf2(a[0] * slo, a[1] * slo);
            *reinterpret_cast<uint32_t*>(g_A2 + ghi * K2 + 768 + col) =
                packbf2(a[2] * shi, a[3] * shi);
        }
    }
}

// ---------------- GEMM2 (split): out = A2[:,K0:K0+KTN*64] @ B2[...]^T --------
// BM=128, BN=128, 256 thr (8 warps, 4Mx2N, warp tile 32x64), 2 CTAs/SM,
// grid (128, 2) = 256 CTAs.  Both operands 3-stage cp.async (96 KB smem),
// PREF=2, wait_group<1>.
//   gemm2<12, 0,   false>: f-part (K=768), no gemm1 dependency -> PDL overlap.
//   gemm2<4,  768, true >: neigh-part (K=256), read-modify-write into out.
static constexpr int G2_TILE = 128 * BK * 2;                 // 16 KB

template <int KTN, int K0, bool ADD>
__global__ void __launch_bounds__(256, 2)
gemm2(float* __restrict__ outF) {
    constexpr uint32_t A_OFF = 0;
    constexpr uint32_t B_OFF = 3 * G2_TILE;

    extern __shared__ char smraw[];
    const uint32_t sb = (smem_u32(smraw) + 127u) & ~127u;

    const int tid  = threadIdx.x;
    const int lane = tid & 31;
    const int w    = tid >> 5;
    const int wm   = w >> 1;            // 0..3  (M dir)
    const int wn   = w & 1;             // 0..1  (N dir)
    const long m0  = (long)blockIdx.x * 128;
    const long n0  = (long)blockIdx.y * 128;

    float acc[2][8][4];
#pragma unroll
    for (int i = 0; i < 2; i++)
#pragma unroll
        for (int j = 0; j < 8; j++)
#pragma unroll
            for (int k = 0; k < 4; k++) acc[i][j][k] = 0.f;

    // ---- tile loaders (A and B symmetric: 128 rows x 64 bf16 cols) ----
    const int rowL = tid >> 3, cL = tid & 7;        // 32 rows per t-step
    const uint32_t offL = (uint32_t)rowL * 128u +
                          ((uint32_t)(cL ^ (rowL & 7)) << 4);
    const __nv_bfloat16* pA = g_A2 + (m0 + rowL) * (size_t)K2 + K0 + cL * 8;
    const __nv_bfloat16* pB = g_B2 + (n0 + rowL) * (size_t)K2 + K0 + cL * 8;
    uint32_t dstA = sb + A_OFF, dstB = sb + B_OFF;
    auto cpT = [&]() {                              // loads next tile (A+B)
#pragma unroll
        for (int t = 0; t < 4; t++) {
            cp16(dstA + offL + (uint32_t)t * (32 * 128u), pA + (size_t)t * 32 * K2);
            cp16(dstB + offL + (uint32_t)t * (32 * 128u), pB + (size_t)t * 32 * K2);
        }
        pA += BK; pB += BK;
        dstA += G2_TILE; if (dstA == sb + A_OFF + 3 * G2_TILE) dstA = sb + A_OFF;
        dstB += G2_TILE; if (dstB == sb + B_OFF + 3 * G2_TILE) dstB = sb + B_OFF;
    };

    // ---- ldmatrix fragment row terms ----
    const int lhi = lane >> 4;
    uint32_t rtA[2], rtB[4];
#pragma unroll
    for (int mi = 0; mi < 2; mi++) {
        const int row = wm * 32 + (lane & 15) + mi * 16;      // 0..127
        rtA[mi] = (uint32_t)row * 128u | ((uint32_t)(row & 7) << 4);
    }
#pragma unroll
    for (int nb = 0; nb < 4; nb++) {
        const int row = wn * 64 + (lane & 15) + nb * 16;      // 0..127
        rtB[nb] = (uint32_t)row * 128u | ((uint32_t)(row & 7) << 4);
    }

    auto compute = [&](uint32_t aBase, uint32_t bBase, int ks0, int ks1) {
#pragma unroll
        for (int ks = ks0; ks < ks1; ks++) {
            const uint32_t cx = (uint32_t)(ks * 2 + lhi) << 4;
            uint32_t af[2][4], bf[4][4];
#pragma unroll
            for (int mi = 0; mi < 2; mi++) ldsm4(af[mi], (aBase + rtA[mi]) ^ cx);
#pragma unroll
            for (int nb = 0; nb < 4; nb++) ldsm4(bf[nb], (bBase + rtB[nb]) ^ cx);
#pragma unroll
            for (int mi = 0; mi < 2; mi++)
#pragma unroll
                for (int nb = 0; nb < 4; nb++) {
                    mma16816(acc[mi][nb * 2],     af[mi], bf[nb][0], bf[nb][2]);
                    mma16816(acc[mi][nb * 2 + 1], af[mi], bf[nb][1], bf[nb][3]);
                }
        }
    };

    // ---------------- prologue: tiles 0,1 in flight -------------------------
    cpT(); cp_commit();
    cpT(); cp_commit();

    // ---------------- main loop (same invariants as gemm1's B pipe) ---------
    uint32_t cAs = sb + A_OFF, cBs = sb + B_OFF;
    for (int kt = 0; kt < KTN; kt++) {
        cp_wait<1>();
        __syncthreads();
        compute(cAs, cBs, 0, 2);
        if (kt + 2 < KTN) cpT();
        cp_commit();
        compute(cAs, cBs, 2, 4);
        cAs += G2_TILE; if (cAs == sb + A_OFF + 3 * G2_TILE) cAs = sb + A_OFF;
        cBs += G2_TILE; if (cBs == sb + B_OFF + 3 * G2_TILE) cBs = sb + B_OFF;
    }

    // ---------------- epilogue: fp32 out (write or accumulate) --------------
#pragma unroll
    for (int mi = 0; mi < 2; mi++) {
        const int rl = wm * 32 + mi * 16 + (lane >> 2);
        const long glo = m0 + rl, ghi = glo + 8;
#pragma unroll
        for (int ni = 0; ni < 8; ni++) {
            const long col = n0 + wn * 64 + ni * 8 + (lane & 3) * 2;
            const float* a = acc[mi][ni];
            float2* dlo = reinterpret_cast<float2*>(outF + glo * DF + col);
            float2* dhi = reinterpret_cast<float2*>(outF + ghi * DF + col);
            if constexpr (ADD) {
                float2 olo = *dlo, ohi = *dhi;
                *dlo = make_float2(olo.x + a[0], olo.y + a[1]);
                *dhi = make_float2(ohi.x + a[2], ohi.y + a[3]);
            } else {
                *dlo = make_float2(a[0], a[1]);
                *dhi = make_float2(a[2], a[3]);
            }
        }
    }
}

static constexpr uint32_t SMEM1 = ASTG * ABYTES + BSTG * BBYTES + 128; // ~112.1 KB
static constexpr uint32_t SMEM2 = 6 * G2_TILE + 128;                   // ~96.1 KB

// ---------------- launch -----------------------------------------------------
extern "C" void kernel_launch(void* const* d_in, const int* in_sizes, int n_in,
                              void* d_out, int out_size) {
    const float* features = nullptr;
    const float* adj      = nullptr;
    const float* W        = nullptr;
    for (int i = 0; i < n_in; i++) {
        if (in_sizes[i] == NN * DF)          features = (const float*)d_in[i];
        else if (in_sizes[i] == DF * 2 * DF) W        = (const float*)d_in[i];
        else                                  adj      = (const float*)d_in[i];
    }

    cudaFuncSetAttribute(gemm1, cudaFuncAttributeMaxDynamicSharedMemorySize, SMEM1);
    cudaFuncSetAttribute(gemm2<12, 0, false>,
                         cudaFuncAttributeMaxDynamicSharedMemorySize, SMEM2);
    cudaFuncSetAttribute(gemm2<4, 768, true>,
                         cudaFuncAttributeMaxDynamicSharedMemorySize, SMEM2);

    prep_fused<<<dim3(NN / 32, DF / 32), dim3(32, 8)>>>(features);
    prep_W<<<DF, 256>>>(W);
    gemm1<<<NN / BMm, 256, SMEM1>>>(adj);

    // gemm2a (f-part, K=768): no dependency on gemm1 -> PDL overlap; its CTAs
    // fill the 48 single-CTA SMs immediately and tail-fill as gemm1 retires.
    {
        cudaLaunchConfig_t cfg = {};
        cfg.gridDim         = dim3(NN / 128, 2);
        cfg.blockDim        = dim3(256);
        cfg.dynamicSmemBytes = SMEM2;
        cfg.stream          = 0;       // same (capture) stream as <<<>>> above
        cudaLaunchAttribute at[1];
        at[0].id = cudaLaunchAttributeProgrammaticStreamSerialization;
        at[0].val.programmaticStreamSerializationAllowed = 1;
        cfg.attrs    = at;
        cfg.numAttrs = 1;
        cudaLaunchKernelEx(&cfg, gemm2<12, 0, false>, (float*)d_out);
    }

    // gemm2b (neigh-part, K=256): normal launch -> stream-ordered after BOTH
    // gemm1 (neigh producer) and gemm2a (out writer); accumulates into out.
    gemm2<4, 768, true><<<dim3(NN / 128, 2), 256, SMEM2>>>((float*)d_out);
}